// round 15
// baseline (speedup 1.0000x reference)
#include <cuda_runtime.h>

// HungarianMatcher cost matrix: C[bs,nq,nt] =
//   5*L1(cxcywh) + 2*focal_class_cost(gathered by tgt_id) - 2*GIoU(xyxy)
//
// R14: single-kernel, zero-duplication fusion.
//  - R13 showed single-launch cuts ~3us of graph/launch gap (0.9us gap).
//  - R12 showed fused focal costs +3.4us because it recomputes the class
//    tile once per target tile (x5). Fix: grid.y removed; each block loops
//    over all 5 target tiles, so its focal tile (12x91) is computed exactly
//    once per logit — same total transcendental work as the old prep, fully
//    overlapped, no global table.
//  - TI=12 -> 1200 blocks = ONE wave (148 SMs x 9 CTAs); focal spread over
//    all 160 threads (~7 evals each); focal body = R12's proven form.
//  - mainloop per tile identical to R11 (best known); tile loop NOT unrolled
//    (5x unroll would exceed I$).

namespace {
constexpr int BS = 16, NQ = 900, NC = 91, NT = 1600;
constexpr int NROWS = BS * NQ;     // 14400
constexpr int TI = 12;             // query rows per block (14400 % 12 == 0)
constexpr int TI_PAD = 14;         // even (LDS.64 alignment)
constexpr int TPB = 160;           // 5 warps
constexpr int TGT_PER_TILE = 2 * TPB;        // 320
constexpr int NTILE_T = NT / TGT_PER_TILE;   // 5
}

// focal class cost (R12's proven form): 2*(pos-neg) + 2
__device__ __forceinline__ float focal_cls2(float x) {
    float p = __fdividef(1.0f, 1.0f + __expf(-x));
    float omp = 1.0f - p;
    float pos = 0.25f * omp * omp * (-__logf(p + 1e-8f));
    float neg = 0.75f * p * p * (-__logf(omp + 1e-8f));
    return 2.0f * (pos - neg) + 2.0f;   // +2 from -2*giou's (-1) term
}

__device__ __forceinline__ float pair_cost(
    const float4 qxy, const float4 qc, const float qarea,
    const float4 txy, const float4 tc, const float tarea,
    const float cls2p)
{
    // L1 on cxcywh
    float bb = fabsf(qc.x - tc.x) + fabsf(qc.y - tc.y)
             + fabsf(qc.z - tc.z) + fabsf(qc.w - tc.w);
    // enclosing box; intersection via identity:
    //   min(q2,t2) - max(q1,t1) = (qw + tw) - ex
    float ex = fmaxf(qxy.z, txy.z) - fminf(qxy.x, txy.x);
    float ey = fmaxf(qxy.w, txy.w) - fminf(qxy.y, txy.y);
    float w  = fmaxf((qc.z + tc.z) - ex, 0.0f);
    float h  = fmaxf((qc.w + tc.w) - ey, 0.0f);
    float inter = w * h;
    float uni = (qarea + tarea) - inter;
    float ae  = ex * ey;
    // inter/uni + uni/ae = (inter*ae + uni^2) / (uni*ae): single RCP per pair
    float num = fmaf(inter, ae, uni * uni);
    float r   = __fdividef(1.0f, uni * ae);
    float c   = fmaf(5.0f, bb, cls2p);
    return fmaf(-2.0f, num * r, c);
}

__global__ void __launch_bounds__(TPB, 9)
cost_kernel(const float* __restrict__ logits,
            const float* __restrict__ pred_boxes,
            const float* __restrict__ tgt_boxes,
            const int*   __restrict__ ids32,
            float* __restrict__ out)
{
    __shared__ float  s_clsT[NC * TI_PAD];  // transposed: [class][q], 5.1 KB
    __shared__ float4 s_qxy[TI];
    __shared__ float4 s_qc[TI];

    const int t  = threadIdx.x;
    const int r0 = blockIdx.x * TI;

    // q-row staging (threads t<12): cxcywh + derived xyxy
    if (t < TI) {
        float4 b = reinterpret_cast<const float4*>(pred_boxes)[r0 + t];
        s_qc[t] = b;
        float4 xy;
        xy.x = b.x - 0.5f * b.z; xy.y = b.y - 0.5f * b.w;
        xy.z = b.x + 0.5f * b.z; xy.w = b.y + 0.5f * b.w;
        s_qxy[t] = xy;
    }

    // focal tile, computed ONCE per block, spread over all 160 threads;
    // LDG coalesced in k.
    for (int k = t; k < TI * NC; k += TPB) {
        int q = k / NC;
        int c = k - q * NC;
        s_clsT[c * TI_PAD + q] = focal_cls2(logits[r0 * NC + k]);
    }

    // tgt_id width detection: int64 in the reference, but jax with x64
    // disabled materializes int32. For nonneg int64 < 2^31 every odd int32
    // word is 0; 8 broadcast loads, P(false positive) = (1/91)^8 ~ 5e-16.
    bool is64 = true;
#pragma unroll
    for (int k = 1; k < 16; k += 2)
        is64 &= (ids32[k] == 0);
    __syncthreads();

    // loop over all 5 target tiles; focal tile reused by each
    for (int tile = 0; tile < NTILE_T; ++tile) {
        const int j0 = tile * TGT_PER_TILE + 2 * t;

        const int id0 = is64 ? ids32[2 * j0]       : ids32[j0];
        const int id1 = is64 ? ids32[2 * (j0 + 1)] : ids32[j0 + 1];

        const float4 t0c = reinterpret_cast<const float4*>(tgt_boxes)[j0];
        const float4 t1c = reinterpret_cast<const float4*>(tgt_boxes)[j0 + 1];
        float4 t0xy, t1xy;
        t0xy.x = t0c.x - 0.5f * t0c.z; t0xy.y = t0c.y - 0.5f * t0c.w;
        t0xy.z = t0c.x + 0.5f * t0c.z; t0xy.w = t0c.y + 0.5f * t0c.w;
        t1xy.x = t1c.x - 0.5f * t1c.z; t1xy.y = t1c.y - 0.5f * t1c.w;
        t1xy.z = t1c.x + 0.5f * t1c.z; t1xy.w = t1c.y + 0.5f * t1c.w;
        const float t0a = t0c.z * t0c.w;
        const float t1a = t1c.z * t1c.w;

        const float* pc0 = s_clsT + id0 * TI_PAD;
        const float* pc1 = s_clsT + id1 * TI_PAD;

        float* orow = out + (size_t)r0 * NT + j0;

#pragma unroll
        for (int q = 0; q < TI; q += 2) {
            const float2 cls0 = *reinterpret_cast<const float2*>(pc0 + q);
            const float2 cls1 = *reinterpret_cast<const float2*>(pc1 + q);

            {   // q-row q
                const float4 qxy = s_qxy[q];
                const float4 qc  = s_qc[q];
                const float  qa  = qc.z * qc.w;
                float c0 = pair_cost(qxy, qc, qa, t0xy, t0c, t0a, cls0.x);
                float c1 = pair_cost(qxy, qc, qa, t1xy, t1c, t1a, cls1.x);
                *reinterpret_cast<float2*>(orow + (size_t)q * NT) = make_float2(c0, c1);
            }
            {   // q-row q+1
                const float4 qxy = s_qxy[q + 1];
                const float4 qc  = s_qc[q + 1];
                const float  qa  = qc.z * qc.w;
                float c0 = pair_cost(qxy, qc, qa, t0xy, t0c, t0a, cls0.y);
                float c1 = pair_cost(qxy, qc, qa, t1xy, t1c, t1a, cls1.y);
                *reinterpret_cast<float2*>(orow + (size_t)(q + 1) * NT) = make_float2(c0, c1);
            }
        }
    }
}

extern "C" void kernel_launch(void* const* d_in, const int* in_sizes, int n_in,
                              void* d_out, int out_size) {
    const float* logits = (const float*)d_in[0];   // [16,900,91]
    const float* pboxes = (const float*)d_in[1];   // [16,900,4]
    const float* tboxes = (const float*)d_in[2];   // [1600,4]
    const int*   ids    = (const int*)d_in[3];     // [1600] (int32 or int64 view)
    float* out = (float*)d_out;                    // [16,900,1600]

    cost_kernel<<<NROWS / TI, TPB>>>(logits, pboxes, tboxes, ids, out);
}

// round 16
// speedup vs baseline: 1.1498x; 1.1498x over previous
#include <cuda_runtime.h>

// HungarianMatcher cost matrix: C[bs,nq,nt] =
//   5*L1(cxcywh) + 2*focal_class_cost(gathered by tgt_id) - 2*GIoU(xyxy)
//
// R15 = R12's kernel VERBATIM (proven 36.0us: grid 800x5, TI=18, minblocks 9,
// t<91 column-wise focal staging, R12 focal form, R11 mainloop) + R13's
// proven single-launch packaging (gap 0.9us vs ~3.5us):
//  - prep launch eliminated; q-row xyxy (t<18), target xyxy/area (registers),
//    and tgt_id width detection inlined — each piece individually proven in
//    R13/R14 at negligible cost.
//  - R14's single-wave long-block layout rejected (tail idle, occ 45.6%).

namespace {
constexpr int BS = 16, NQ = 900, NC = 91, NT = 1600;
constexpr int NROWS = BS * NQ;     // 14400
constexpr int TI = 18;             // query rows per block (14400 % 18 == 0)
constexpr int TI_PAD = 22;         // even (LDS.64 alignment), gcd(22,32)=2
constexpr int TPB = 160;           // 5 warps
constexpr int TGT_PER_BLK = 2 * TPB;       // 320
constexpr int NTILE_T = NT / TGT_PER_BLK;  // 5
}

// focal class cost (R12's proven form): 2*(pos-neg) + 2
__device__ __forceinline__ float focal_cls2(float x) {
    float p = __fdividef(1.0f, 1.0f + __expf(-x));
    float omp = 1.0f - p;
    float pos = 0.25f * omp * omp * (-__logf(p + 1e-8f));
    float neg = 0.75f * p * p * (-__logf(omp + 1e-8f));
    return 2.0f * (pos - neg) + 2.0f;   // +2 from -2*giou's (-1) term
}

__device__ __forceinline__ float pair_cost(
    const float4 qxy, const float4 qc, const float qarea,
    const float4 txy, const float4 tc, const float tarea,
    const float cls2p)
{
    // L1 on cxcywh
    float bb = fabsf(qc.x - tc.x) + fabsf(qc.y - tc.y)
             + fabsf(qc.z - tc.z) + fabsf(qc.w - tc.w);
    // enclosing box; intersection via identity:
    //   min(q2,t2) - max(q1,t1) = (qw + tw) - ex
    float ex = fmaxf(qxy.z, txy.z) - fminf(qxy.x, txy.x);
    float ey = fmaxf(qxy.w, txy.w) - fminf(qxy.y, txy.y);
    float w  = fmaxf((qc.z + tc.z) - ex, 0.0f);
    float h  = fmaxf((qc.w + tc.w) - ey, 0.0f);
    float inter = w * h;
    float uni = (qarea + tarea) - inter;
    float ae  = ex * ey;
    // inter/uni + uni/ae = (inter*ae + uni^2) / (uni*ae): single RCP per pair
    float num = fmaf(inter, ae, uni * uni);
    float r   = __fdividef(1.0f, uni * ae);
    float c   = fmaf(5.0f, bb, cls2p);
    return fmaf(-2.0f, num * r, c);
}

__global__ void __launch_bounds__(TPB, 9)
cost_kernel(const float* __restrict__ logits,
            const float* __restrict__ pred_boxes,
            const float* __restrict__ tgt_boxes,
            const int*   __restrict__ ids32,
            float* __restrict__ out)
{
    __shared__ float  s_clsT[NC * TI_PAD];  // transposed: [class][q], 8.0 KB
    __shared__ float4 s_qxy[TI];
    __shared__ float4 s_qc[TI];

    const int t  = threadIdx.x;
    const int r0 = blockIdx.x * TI;
    const int j0 = blockIdx.y * TGT_PER_BLK + 2 * t;

    // Focal staging (R12's exact proven form): threads t<91 each own class
    // column t; LDG coalesced across t within each q row; 18 independent
    // LDG+MUFU chains per thread (good MLP). Threads 91..108 stage q rows.
    if (t < NC) {
#pragma unroll
        for (int q = 0; q < TI; ++q)
            s_clsT[t * TI_PAD + q] = focal_cls2(logits[(r0 + q) * NC + t]);
    } else if (t < NC + TI) {
        int qq = t - NC;
        float4 b = reinterpret_cast<const float4*>(pred_boxes)[r0 + qq];
        s_qc[qq] = b;
        float4 xy;
        xy.x = b.x - 0.5f * b.z; xy.y = b.y - 0.5f * b.w;
        xy.z = b.x + 0.5f * b.z; xy.w = b.y + 0.5f * b.w;
        s_qxy[qq] = xy;
    }

    // tgt_id width detection: int64 in the reference, but jax with x64
    // disabled materializes int32. For nonneg int64 < 2^31 every odd int32
    // word is 0; 8 broadcast loads, P(false positive) = (1/91)^8 ~ 5e-16.
    bool is64 = true;
#pragma unroll
    for (int k = 1; k < 16; k += 2)
        is64 &= (ids32[k] == 0);
    const int id0 = is64 ? ids32[2 * j0]       : ids32[j0];
    const int id1 = is64 ? ids32[2 * (j0 + 1)] : ids32[j0 + 1];

    // per-thread target constants in registers (must stay resident — see R5)
    const float4 t0c = reinterpret_cast<const float4*>(tgt_boxes)[j0];
    const float4 t1c = reinterpret_cast<const float4*>(tgt_boxes)[j0 + 1];
    float4 t0xy, t1xy;
    t0xy.x = t0c.x - 0.5f * t0c.z; t0xy.y = t0c.y - 0.5f * t0c.w;
    t0xy.z = t0c.x + 0.5f * t0c.z; t0xy.w = t0c.y + 0.5f * t0c.w;
    t1xy.x = t1c.x - 0.5f * t1c.z; t1xy.y = t1c.y - 0.5f * t1c.w;
    t1xy.z = t1c.x + 0.5f * t1c.z; t1xy.w = t1c.y + 0.5f * t1c.w;
    const float t0a = t0c.z * t0c.w;
    const float t1a = t1c.z * t1c.w;
    __syncthreads();

    // gather bases: one LDS.64 per target fetches cls for (q, q+1)
    const float* pc0 = s_clsT + id0 * TI_PAD;
    const float* pc1 = s_clsT + id1 * TI_PAD;

    float* orow = out + (size_t)r0 * NT + j0;

#pragma unroll
    for (int q = 0; q < TI; q += 2) {
        const float2 cls0 = *reinterpret_cast<const float2*>(pc0 + q);
        const float2 cls1 = *reinterpret_cast<const float2*>(pc1 + q);

        {   // q-row q
            const float4 qxy = s_qxy[q];
            const float4 qc  = s_qc[q];
            const float  qa  = qc.z * qc.w;
            float c0 = pair_cost(qxy, qc, qa, t0xy, t0c, t0a, cls0.x);
            float c1 = pair_cost(qxy, qc, qa, t1xy, t1c, t1a, cls1.x);
            *reinterpret_cast<float2*>(orow + (size_t)q * NT) = make_float2(c0, c1);
        }
        {   // q-row q+1
            const float4 qxy = s_qxy[q + 1];
            const float4 qc  = s_qc[q + 1];
            const float  qa  = qc.z * qc.w;
            float c0 = pair_cost(qxy, qc, qa, t0xy, t0c, t0a, cls0.y);
            float c1 = pair_cost(qxy, qc, qa, t1xy, t1c, t1a, cls1.y);
            *reinterpret_cast<float2*>(orow + (size_t)(q + 1) * NT) = make_float2(c0, c1);
        }
    }
}

extern "C" void kernel_launch(void* const* d_in, const int* in_sizes, int n_in,
                              void* d_out, int out_size) {
    const float* logits = (const float*)d_in[0];   // [16,900,91]
    const float* pboxes = (const float*)d_in[1];   // [16,900,4]
    const float* tboxes = (const float*)d_in[2];   // [1600,4]
    const int*   ids    = (const int*)d_in[3];     // [1600] (int32 or int64 view)
    float* out = (float*)d_out;                    // [16,900,1600]

    dim3 grid(NROWS / TI, NTILE_T);
    cost_kernel<<<grid, TPB>>>(logits, pboxes, tboxes, ids, out);
}